// round 5
// baseline (speedup 1.0000x reference)
#include <cuda_runtime.h>
#include <cuda_bf16.h>
#include <stdint.h>
#include <math.h>

#define B_    4
#define V_    128
#define H_    256
#define NH_   8
#define HD_   32
#define L_    4
#define BV_   512
#define EROWS_ 65536

// ---------------- device scratch ----------------
__device__ float g_e[EROWS_ * H_];            // 64 MB edge features (updated in place)
__device__ float g_etmp[EROWS_ * H_];         // 64 MB pre-BN edge features (fp32)
__device__ float g_x[BV_ * H_];
__device__ float g_xw[BV_ * NH_ * H_];
__device__ float g_as_[BV_ * NH_];
__device__ float g_ad_[BV_ * NH_];
__device__ float g_alphar[B_ * V_ * V_ * NH_];
__device__ float g_Vx[BV_ * H_];
__device__ float g_Q[BV_ * H_];
__device__ float g_K[BV_ * H_];
__device__ float g_Vt[BV_ * H_];
__device__ float g_att[BV_ * H_];
__device__ float g_xtmp[BV_ * H_];
__device__ float g_gate[EROWS_];
__device__ float g_bnsum[H_], g_bnsumsq[H_];
__device__ float g_nsum[H_], g_nsumsq[H_];
__device__ float g_escale[H_], g_eshift[H_];
__device__ __nv_bfloat16 g_Wthi[5 * H_ * H_]; // [mat][n][k]
__device__ __nv_bfloat16 g_Wtlo[5 * H_ * H_];

// ---------------- shared-mem layout for big kernels ----------------
struct EdgeSmem {
    __nv_bfloat16 Ah[128][264];
    __nv_bfloat16 Al[128][264];
    __nv_bfloat16 Bh[256][40];
    __nv_bfloat16 Bl[256][40];
    float sgate[128];
    float scs[256];
    float scs2[256];
    float sout[128][2];
};

#define MMA16816(d, a0, a1, a2, a3, b0, b1)                                    \
    asm volatile(                                                              \
        "mma.sync.aligned.m16n8k16.row.col.f32.bf16.bf16.f32 "                 \
        "{%0,%1,%2,%3}, {%4,%5,%6,%7}, {%8,%9}, {%0,%1,%2,%3};"                \
        : "+f"(d[0]), "+f"(d[1]), "+f"(d[2]), "+f"(d[3])                       \
        : "r"(a0), "r"(a1), "r"(a2), "r"(a3), "r"(b0), "r"(b1))

__device__ __forceinline__ float sigf(float v) { return 1.f / (1.f + __expf(-v)); }

// Prologue + MMA mainloop shared by edge-layer and head kernels.
// apply_res: fuse e += relu(sc*etmp+sh). write_e: write updated e back.
__device__ __forceinline__ void edge_prolog_mma(
    EdgeSmem& S, int m0, int tid, int apply_res, int write_e,
    const __nv_bfloat16* __restrict__ Bthi, const __nv_bfloat16* __restrict__ Btlo,
    float acc[4][8][4])
{
    // ---- prologue: residual + stage A (split bf16) ----
    #pragma unroll
    for (int i = 0; i < 32; ++i) {
        int gidx = tid + i * 256;            // 0..8191 float4 groups
        int row = gidx >> 6;
        int col = (gidx & 63) << 2;
        size_t base = (size_t)(m0 + row) * H_ + col;
        float4 ev = *(const float4*)(g_e + base);
        if (apply_res) {
            float4 t = *(const float4*)(g_etmp + base);
            float4 sc = *(const float4*)(g_escale + col);
            float4 sh = *(const float4*)(g_eshift + col);
            ev.x += fmaxf(t.x * sc.x + sh.x, 0.f);
            ev.y += fmaxf(t.y * sc.y + sh.y, 0.f);
            ev.z += fmaxf(t.z * sc.z + sh.z, 0.f);
            ev.w += fmaxf(t.w * sc.w + sh.w, 0.f);
            if (write_e) *(float4*)(g_e + base) = ev;
        }
        __nv_bfloat16 h0 = __float2bfloat16_rn(ev.x);
        __nv_bfloat16 h1 = __float2bfloat16_rn(ev.y);
        __nv_bfloat16 h2 = __float2bfloat16_rn(ev.z);
        __nv_bfloat16 h3 = __float2bfloat16_rn(ev.w);
        __nv_bfloat16 l0 = __float2bfloat16_rn(ev.x - __bfloat162float(h0));
        __nv_bfloat16 l1 = __float2bfloat16_rn(ev.y - __bfloat162float(h1));
        __nv_bfloat16 l2 = __float2bfloat16_rn(ev.z - __bfloat162float(h2));
        __nv_bfloat16 l3 = __float2bfloat16_rn(ev.w - __bfloat162float(h3));
        *(__nv_bfloat162*)&S.Ah[row][col]     = __halves2bfloat162(h0, h1);
        *(__nv_bfloat162*)&S.Ah[row][col + 2] = __halves2bfloat162(h2, h3);
        *(__nv_bfloat162*)&S.Al[row][col]     = __halves2bfloat162(l0, l1);
        *(__nv_bfloat162*)&S.Al[row][col + 2] = __halves2bfloat162(l2, l3);
    }

    const int lane = tid & 31, warp = tid >> 5;
    const int wm = warp >> 2, wn = warp & 3;     // warp grid 2 x 4, warp tile 64x64
    const int g = lane >> 2, q2 = (lane & 3) * 2;

    for (int k0 = 0; k0 < 256; k0 += 32) {
        __syncthreads();
        // stage B [256 n][32 k] hi + lo
        #pragma unroll
        for (int i = 0; i < 4; ++i) {
            int idx = tid + i * 256;         // 0..1023
            int n = idx >> 2, seg = (idx & 3) * 8;
            *(uint4*)&S.Bh[n][seg] = *(const uint4*)(Bthi + n * 256 + k0 + seg);
            *(uint4*)&S.Bl[n][seg] = *(const uint4*)(Btlo + n * 256 + k0 + seg);
        }
        __syncthreads();
        #pragma unroll
        for (int k16 = 0; k16 < 32; k16 += 16) {
            int kk = k0 + k16 + q2;
            uint32_t ah[4][4], al[4][4];
            #pragma unroll
            for (int mt = 0; mt < 4; ++mt) {
                int ar = wm * 64 + mt * 16 + g;
                ah[mt][0] = *(const uint32_t*)&S.Ah[ar][kk];
                ah[mt][1] = *(const uint32_t*)&S.Ah[ar + 8][kk];
                ah[mt][2] = *(const uint32_t*)&S.Ah[ar][kk + 8];
                ah[mt][3] = *(const uint32_t*)&S.Ah[ar + 8][kk + 8];
                al[mt][0] = *(const uint32_t*)&S.Al[ar][kk];
                al[mt][1] = *(const uint32_t*)&S.Al[ar + 8][kk];
                al[mt][2] = *(const uint32_t*)&S.Al[ar][kk + 8];
                al[mt][3] = *(const uint32_t*)&S.Al[ar + 8][kk + 8];
            }
            int kb = k16 + q2;
            #pragma unroll
            for (int nt = 0; nt < 8; ++nt) {
                int br = wn * 64 + nt * 8 + g;
                uint32_t bh0 = *(const uint32_t*)&S.Bh[br][kb];
                uint32_t bh1 = *(const uint32_t*)&S.Bh[br][kb + 8];
                uint32_t bl0 = *(const uint32_t*)&S.Bl[br][kb];
                uint32_t bl1 = *(const uint32_t*)&S.Bl[br][kb + 8];
                #pragma unroll
                for (int mt = 0; mt < 4; ++mt) {
                    MMA16816(acc[mt][nt], ah[mt][0], ah[mt][1], ah[mt][2], ah[mt][3], bh0, bh1);
                    MMA16816(acc[mt][nt], al[mt][0], al[mt][1], al[mt][2], al[mt][3], bh0, bh1);
                    MMA16816(acc[mt][nt], ah[mt][0], ah[mt][1], ah[mt][2], ah[mt][3], bl0, bl1);
                }
            }
        }
    }
    __syncthreads();
}

// ---- fused edge layer: residual + etmp GEMM + gate/BN stats ----
__global__ __launch_bounds__(256, 1) void edge_layer_kernel(
    int lmat, int apply_res, const float* __restrict__ bias)
{
    extern __shared__ char smem_raw[];
    EdgeSmem& S = *reinterpret_cast<EdgeSmem*>(smem_raw);
    int tid = threadIdx.x;
    int m0 = blockIdx.x * 128;

    if (tid < 128) S.sgate[tid] = 0.f;
    S.scs[tid] = 0.f; S.scs2[tid] = 0.f;

    float acc[4][8][4];
    #pragma unroll
    for (int a = 0; a < 4; ++a)
        #pragma unroll
        for (int b = 0; b < 8; ++b)
            #pragma unroll
            for (int c = 0; c < 4; ++c) acc[a][b][c] = 0.f;

    edge_prolog_mma(S, m0, tid, apply_res, 1,
                    g_Wthi + lmat * H_ * H_, g_Wtlo + lmat * H_ * H_, acc);

    const int lane = tid & 31, warp = tid >> 5;
    const int wm = warp >> 2, wn = warp & 3;
    const int g = lane >> 2, q2 = (lane & 3) * 2;

    int bi = m0 >> 7;
    int b = bi >> 7;
    const float* vxi = g_Vx + bi * H_;
    const float* vxbase = g_Vx + b * V_ * H_;

    float basev[8][2];
    #pragma unroll
    for (int nt = 0; nt < 8; ++nt) {
        int c = wn * 64 + nt * 8 + q2;
        basev[nt][0] = bias[c] + vxi[c];
        basev[nt][1] = bias[c + 1] + vxi[c + 1];
    }
    float colsum[8][2], colsum2[8][2];
    #pragma unroll
    for (int nt = 0; nt < 8; ++nt) {
        colsum[nt][0] = colsum[nt][1] = 0.f;
        colsum2[nt][0] = colsum2[nt][1] = 0.f;
    }

    #pragma unroll
    for (int mt = 0; mt < 4; ++mt) {
        #pragma unroll
        for (int rr = 0; rr < 2; ++rr) {
            int rin = wm * 64 + mt * 16 + g + rr * 8;
            int r = m0 + rin;
            int jn = r & 127;
            const float* vxj = vxbase + jn * H_;
            float rowsig = 0.f;
            #pragma unroll
            for (int nt = 0; nt < 8; ++nt) {
                int c = wn * 64 + nt * 8 + q2;
                float2 vj = *(const float2*)(vxj + c);
                float v0 = acc[mt][nt][rr * 2 + 0] + basev[nt][0] + vj.x;
                float v1 = acc[mt][nt][rr * 2 + 1] + basev[nt][1] + vj.y;
                rowsig += sigf(v0) + sigf(v1);
                colsum[nt][0] += v0; colsum[nt][1] += v1;
                colsum2[nt][0] += v0 * v0; colsum2[nt][1] += v1 * v1;
                *(float2*)(g_etmp + (size_t)r * H_ + c) = make_float2(v0, v1);
            }
            atomicAdd(&S.sgate[rin], rowsig);
        }
    }
    #pragma unroll
    for (int nt = 0; nt < 8; ++nt) {
        int c = wn * 64 + nt * 8 + q2;
        atomicAdd(&S.scs[c], colsum[nt][0]);
        atomicAdd(&S.scs[c + 1], colsum[nt][1]);
        atomicAdd(&S.scs2[c], colsum2[nt][0]);
        atomicAdd(&S.scs2[c + 1], colsum2[nt][1]);
    }
    __syncthreads();
    if (tid < 128) g_gate[m0 + tid] = S.sgate[tid];
    atomicAdd(&g_bnsum[tid], S.scs[tid]);
    atomicAdd(&g_bnsumsq[tid], S.scs2[tid]);
}

// ---- fused head: residual + relu(e@Wm+bm)@Wout ----
__global__ __launch_bounds__(256, 1) void head_kernel(
    const float* __restrict__ bm, const float* __restrict__ Wout, float* __restrict__ out)
{
    extern __shared__ char smem_raw[];
    EdgeSmem& S = *reinterpret_cast<EdgeSmem*>(smem_raw);
    int tid = threadIdx.x;
    int m0 = blockIdx.x * 128;

    if (tid < 128) { S.sout[tid][0] = 0.f; S.sout[tid][1] = 0.f; }

    float acc[4][8][4];
    #pragma unroll
    for (int a = 0; a < 4; ++a)
        #pragma unroll
        for (int b = 0; b < 8; ++b)
            #pragma unroll
            for (int c = 0; c < 4; ++c) acc[a][b][c] = 0.f;

    edge_prolog_mma(S, m0, tid, 1, 0,
                    g_Wthi + 4 * H_ * H_, g_Wtlo + 4 * H_ * H_, acc);

    const int lane = tid & 31, warp = tid >> 5;
    const int wm = warp >> 2, wn = warp & 3;
    const int g = lane >> 2, q2 = (lane & 3) * 2;

    float bmv[8][2], w0[8][2], w1[8][2];
    #pragma unroll
    for (int nt = 0; nt < 8; ++nt) {
        int c = wn * 64 + nt * 8 + q2;
        bmv[nt][0] = bm[c];     bmv[nt][1] = bm[c + 1];
        w0[nt][0] = Wout[c * 2];       w0[nt][1] = Wout[(c + 1) * 2];
        w1[nt][0] = Wout[c * 2 + 1];   w1[nt][1] = Wout[(c + 1) * 2 + 1];
    }

    #pragma unroll
    for (int mt = 0; mt < 4; ++mt) {
        #pragma unroll
        for (int rr = 0; rr < 2; ++rr) {
            int rin = wm * 64 + mt * 16 + g + rr * 8;
            float p0 = 0.f, p1 = 0.f;
            #pragma unroll
            for (int nt = 0; nt < 8; ++nt) {
                float v0 = fmaxf(acc[mt][nt][rr * 2 + 0] + bmv[nt][0], 0.f);
                float v1 = fmaxf(acc[mt][nt][rr * 2 + 1] + bmv[nt][1], 0.f);
                p0 += v0 * w0[nt][0] + v1 * w0[nt][1];
                p1 += v0 * w1[nt][0] + v1 * w1[nt][1];
            }
            atomicAdd(&S.sout[rin][0], p0);
            atomicAdd(&S.sout[rin][1], p1);
        }
    }
    __syncthreads();
    int rr = tid >> 1, cc = tid & 1;
    if (rr < 128) atomicAdd(&out[(m0 + rr) * 2 + cc], S.sout[rr][cc]);
}

// ---------------- weight prep ----------------
__global__ void wprep_kernel(const float* __restrict__ Wu, const float* __restrict__ Wm)
{
    int idx = blockIdx.x * blockDim.x + threadIdx.x;
    if (idx >= 5 * H_ * H_) return;
    int mat = idx >> 16;
    int k = (idx >> 8) & 255;
    int n = idx & 255;
    float v = (mat < 4) ? Wu[mat * H_ * H_ + k * H_ + n] : Wm[k * H_ + n];
    __nv_bfloat16 hi = __float2bfloat16_rn(v);
    __nv_bfloat16 lo = __float2bfloat16_rn(v - __bfloat162float(hi));
    g_Wthi[mat * H_ * H_ + n * H_ + k] = hi;
    g_Wtlo[mat * H_ * H_ + n * H_ + k] = lo;
}

// ---------------- small SIMT GEMM body ----------------
__device__ __forceinline__ void gemm32_body(
    const float* __restrict__ A, int lda, const float* __restrict__ Bm, int ldb,
    int kbase, int klen, int m0, int n0, int tid,
    float (*As)[33], float (*Bs)[36], float acc[2][2])
{
    const int tx = tid & 15, ty = tid >> 4;
    for (int k0 = 0; k0 < klen; k0 += 32) {
        int ar = tid >> 3, ac = (tid & 7) << 2;
        float4 av = *(const float4*)(A + (size_t)(m0 + ar) * lda + kbase + k0 + ac);
        As[ac + 0][ar] = av.x; As[ac + 1][ar] = av.y;
        As[ac + 2][ar] = av.z; As[ac + 3][ar] = av.w;
        *(float4*)(&Bs[ar][ac]) = *(const float4*)(Bm + (size_t)(kbase + k0 + ar) * ldb + n0 + ac);
        __syncthreads();
        #pragma unroll
        for (int k = 0; k < 32; ++k) {
            float a0 = As[k][ty * 2], a1 = As[k][ty * 2 + 1];
            float b0 = Bs[k][tx * 2], b1 = Bs[k][tx * 2 + 1];
            acc[0][0] += a0 * b0; acc[0][1] += a0 * b1;
            acc[1][0] += a1 * b0; acc[1][1] += a1 * b1;
        }
        __syncthreads();
    }
}

// ---------------- GAT embedding ----------------
__global__ void gat_prep_kernel(const float* __restrict__ coord, const float* __restrict__ Wg,
                                const float* __restrict__ asrc, const float* __restrict__ adst)
{
    int bv = blockIdx.x;
    int tid = threadIdx.x;
    int nh = tid >> 5, lane = tid & 31;
    float c0 = coord[bv * 2], c1 = coord[bv * 2 + 1];
    float s1 = 0.f, s2 = 0.f;
    #pragma unroll
    for (int j = 0; j < 8; ++j) {
        int h = lane + j * 32;
        float w = c0 * Wg[nh * H_ + h] + c1 * Wg[NH_ * H_ + nh * H_ + h];
        g_xw[(bv * NH_ + nh) * H_ + h] = w;
        s1 += w * asrc[nh * H_ + h];
        s2 += w * adst[nh * H_ + h];
    }
    #pragma unroll
    for (int o = 16; o > 0; o >>= 1) {
        s1 += __shfl_down_sync(0xffffffffu, s1, o);
        s2 += __shfl_down_sync(0xffffffffu, s2, o);
    }
    if (lane == 0) { g_as_[bv * NH_ + nh] = s1; g_ad_[bv * NH_ + nh] = s2; }
}

__global__ void gat_softmax_kernel(const int* __restrict__ xe)
{
    int bt = blockIdx.x;
    int b = bt >> 7, t = bt & 127;
    int tid = threadIdx.x;
    int nh = tid >> 5, lane = tid & 31;
    float ad = g_ad_[(b * V_ + t) * NH_ + nh];
    float zv[4]; bool mv[4];
    #pragma unroll
    for (int k = 0; k < 4; ++k) {
        int s = lane + k * 32;
        bool m = (xe[(b * V_ + s) * V_ + t] != 0) || (s == t);
        float z = ad + g_as_[(b * V_ + s) * NH_ + nh];
        z = z > 0.f ? z : 0.2f * z;
        zv[k] = m ? z : -1e30f;
        mv[k] = m;
    }
    float mx = fmaxf(fmaxf(zv[0], zv[1]), fmaxf(zv[2], zv[3]));
    #pragma unroll
    for (int o = 16; o > 0; o >>= 1) mx = fmaxf(mx, __shfl_xor_sync(0xffffffffu, mx, o));
    float ez[4]; float ssum = 0.f;
    #pragma unroll
    for (int k = 0; k < 4; ++k) {
        ez[k] = mv[k] ? __expf(zv[k] - mx) : 0.f;
        ssum += ez[k];
    }
    #pragma unroll
    for (int o = 16; o > 0; o >>= 1) ssum += __shfl_xor_sync(0xffffffffu, ssum, o);
    float inv = 0.125f / ssum;
    #pragma unroll
    for (int k = 0; k < 4; ++k) {
        int s = lane + k * 32;
        g_alphar[b * (V_ * V_ * NH_) + t * (V_ * NH_) + s * NH_ + nh] = ez[k] * inv;
    }
}

__global__ void xinit_kernel(const float* __restrict__ bg)
{
    int i = blockIdx.x * blockDim.x + threadIdx.x;   // 131072
    g_x[i] = bg[i & 255];
}

// split-K GAT aggregation: g_x += alphar[b] @ xw[b] (atomic)
__global__ __launch_bounds__(256) void gat_agg_kernel()
{
    __shared__ float As[32][33];
    __shared__ float Bs[32][36];
    int z = blockIdx.z;                  // b*4 + ksplit
    int b = z >> 2, kz = z & 3;
    const float* A = g_alphar + b * (V_ * V_ * NH_);
    const float* Bm = g_xw + b * (V_ * NH_ * H_);
    float* O = g_x + b * (V_ * H_);
    float acc[2][2] = {{0.f, 0.f}, {0.f, 0.f}};
    int m0 = blockIdx.x * 32, n0 = blockIdx.y * 32, tid = threadIdx.x;
    gemm32_body(A, V_ * NH_, Bm, H_, kz * 256, 256, m0, n0, tid, As, Bs, acc);
    int tx = tid & 15, ty = tid >> 4;
    #pragma unroll
    for (int i = 0; i < 2; ++i)
        #pragma unroll
        for (int j = 0; j < 2; ++j)
            atomicAdd(&O[(m0 + ty * 2 + i) * H_ + n0 + tx * 2 + j], acc[i][j]);
}

// ---------------- edge embedding ----------------
__global__ void edge_embed_kernel(const float* __restrict__ ev, const int* __restrict__ xe,
                                  const float* __restrict__ Wev, const float* __restrict__ emb)
{
    int row = blockIdx.x, tid = threadIdx.x;
    float val;
    if (tid < 128) val = ev[row] * Wev[tid];
    else val = emb[xe[row] * 128 + (tid - 128)];
    g_e[(size_t)row * H_ + tid] = val;
}

// ---------------- per-layer small kernels ----------------
__global__ void zero_sums_kernel()
{
    int i = threadIdx.x;
    g_bnsum[i] = 0.f; g_bnsumsq[i] = 0.f; g_nsum[i] = 0.f; g_nsumsq[i] = 0.f;
}

__global__ __launch_bounds__(256) void node_lin4_kernel(
    const float* __restrict__ W0, const float* __restrict__ W1,
    const float* __restrict__ W2, const float* __restrict__ W3,
    const float* __restrict__ b0, const float* __restrict__ b1,
    const float* __restrict__ b2, const float* __restrict__ b3)
{
    __shared__ float As[32][33];
    __shared__ float Bs[32][36];
    int z = blockIdx.z;
    const float* W = (z == 0) ? W0 : (z == 1) ? W1 : (z == 2) ? W2 : W3;
    const float* bb = (z == 0) ? b0 : (z == 1) ? b1 : (z == 2) ? b2 : b3;
    float* O = (z == 0) ? g_Vx : (z == 1) ? g_Q : (z == 2) ? g_K : g_Vt;
    float acc[2][2] = {{0.f, 0.f}, {0.f, 0.f}};
    int m0 = blockIdx.x * 32, n0 = blockIdx.y * 32, tid = threadIdx.x;
    gemm32_body(g_x, H_, W, H_, 0, H_, m0, n0, tid, As, Bs, acc);
    int tx = tid & 15, ty = tid >> 4;
    #pragma unroll
    for (int i = 0; i < 2; ++i)
        #pragma unroll
        for (int j = 0; j < 2; ++j) {
            int c = n0 + tx * 2 + j;
            O[(m0 + ty * 2 + i) * H_ + c] = acc[i][j] + bb[c];
        }
}

__global__ __launch_bounds__(256) void node_lin1_kernel(
    const float* __restrict__ W, const float* __restrict__ bb)
{
    __shared__ float As[32][33];
    __shared__ float Bs[32][36];
    float acc[2][2] = {{0.f, 0.f}, {0.f, 0.f}};
    int m0 = blockIdx.x * 32, n0 = blockIdx.y * 32, tid = threadIdx.x;
    gemm32_body(g_att, H_, W, H_, 0, H_, m0, n0, tid, As, Bs, acc);
    int tx = tid & 15, ty = tid >> 4;
    #pragma unroll
    for (int i = 0; i < 2; ++i)
        #pragma unroll
        for (int j = 0; j < 2; ++j) {
            int c = n0 + tx * 2 + j;
            g_xtmp[(m0 + ty * 2 + i) * H_ + c] = acc[i][j] + bb[c];
        }
}

__global__ void attn_kernel()
{
    int i = blockIdx.x, nh = blockIdx.y, b = blockIdx.z;
    int tid = threadIdx.x;
    __shared__ float Qs[32];
    __shared__ float sh[8];
    __shared__ float at[128];
    __shared__ float pacc[4][32];
    if (tid < 32) Qs[tid] = g_Q[(b * V_ + i) * H_ + nh * HD_ + tid];
    __syncthreads();
    const float* Kr = &g_K[(b * V_ + tid) * H_ + nh * HD_];
    float sc = 0.f;
    #pragma unroll
    for (int d = 0; d < HD_; ++d) sc += Qs[d] * Kr[d];
    float gm = g_gate[(b * V_ + i) * V_ + tid] * (1.f / 256.f);
    sc *= 0.17677669529663687f * gm;
    float v = sc;
    #pragma unroll
    for (int o = 16; o > 0; o >>= 1) v = fmaxf(v, __shfl_down_sync(0xffffffffu, v, o));
    if ((tid & 31) == 0) sh[tid >> 5] = v;
    __syncthreads();
    float mx = fmaxf(fmaxf(sh[0], sh[1]), fmaxf(sh[2], sh[3]));
    float ez = __expf(sc - mx);
    v = ez;
    #pragma unroll
    for (int o = 16; o > 0; o >>= 1) v += __shfl_down_sync(0xffffffffu, v, o);
    __syncthreads();
    if ((tid & 31) == 0) sh[tid >> 5] = v;
    __syncthreads();
    float ssum = sh[0] + sh[1] + sh[2] + sh[3];
    at[tid] = ez / ssum;
    __syncthreads();
    int d = tid & 31, part = tid >> 5;
    float acc = 0.f;
    int j0 = part * 32;
    #pragma unroll
    for (int j = 0; j < 32; ++j)
        acc += at[j0 + j] * g_Vt[(b * V_ + j0 + j) * H_ + nh * HD_ + d];
    pacc[part][d] = acc;
    __syncthreads();
    if (tid < 32)
        g_att[(b * V_ + i) * H_ + nh * HD_ + tid] =
            pacc[0][tid] + pacc[1][tid] + pacc[2][tid] + pacc[3][tid];
}

__global__ void node_bn_stats_kernel()
{
    int c = threadIdx.x;
    int r0 = blockIdx.x * 32;
    float s = 0.f, s2 = 0.f;
    for (int r = r0; r < r0 + 32; ++r) {
        float v = g_xtmp[r * H_ + c];
        s += v; s2 += v * v;
    }
    atomicAdd(&g_nsum[c], s);
    atomicAdd(&g_nsumsq[c], s2);
}

__global__ void node_update_kernel(const float* __restrict__ gam, const float* __restrict__ bet)
{
    int r = blockIdx.x, c = threadIdx.x;
    float mean = g_nsum[c] * (1.f / 512.f);
    float var = g_nsumsq[c] * (1.f / 512.f) - mean * mean;
    float sc = gam[c] * rsqrtf(fmaxf(var, 0.f) + 1e-5f);
    float shf = bet[c] - mean * sc;
    float v = g_xtmp[r * H_ + c] * sc + shf;
    g_x[r * H_ + c] += fmaxf(v, 0.f);
}

__global__ void edge_bn_finalize_kernel(const float* __restrict__ gam, const float* __restrict__ bet)
{
    int c = threadIdx.x;
    float mean = g_bnsum[c] * (1.f / 65536.f);
    float var = g_bnsumsq[c] * (1.f / 65536.f) - mean * mean;
    float sc = gam[c] * rsqrtf(fmaxf(var, 0.f) + 1e-5f);
    g_escale[c] = sc;
    g_eshift[c] = bet[c] - mean * sc;
}

__global__ void out_init_kernel(const float* __restrict__ bo, float* __restrict__ out)
{
    int i = blockIdx.x * blockDim.x + threadIdx.x;
    out[i] = bo[i & 1];
}

// ---------------- launch ----------------
extern "C" void kernel_launch(void* const* d_in, const int* in_sizes, int n_in,
                              void* d_out, int out_size)
{
    (void)in_sizes; (void)n_in; (void)out_size;
    const int*   x_edges  = (const int*)  d_in[0];
    const float* x_ev     = (const float*)d_in[1];
    const float* coord    = (const float*)d_in[3];
    const float* W_gat    = (const float*)d_in[4];
    const float* att_src  = (const float*)d_in[5];
    const float* att_dst  = (const float*)d_in[6];
    const float* b_gat    = (const float*)d_in[7];
    const float* W_ev     = (const float*)d_in[8];
    const float* emb_e    = (const float*)d_in[9];
    const float* Wu   = (const float*)d_in[10];
    const float* Wv   = (const float*)d_in[11];
    const float* Wq   = (const float*)d_in[12];
    const float* Wk   = (const float*)d_in[13];
    const float* Wval = (const float*)d_in[14];
    const float* Wo   = (const float*)d_in[15];
    const float* bu   = (const float*)d_in[16];
    const float* bv   = (const float*)d_in[17];
    const float* bq   = (const float*)d_in[18];
    const float* bk   = (const float*)d_in[19];
    const float* bval = (const float*)d_in[20];
    const float* bo   = (const float*)d_in[21];
    const float* g_node  = (const float*)d_in[22];
    const float* be_node = (const float*)d_in[23];
    const float* g_edge  = (const float*)d_in[24];
    const float* be_edge = (const float*)d_in[25];
    const float* Wm   = (const float*)d_in[26];
    const float* bm   = (const float*)d_in[27];
    const float* Wout = (const float*)d_in[28];
    const float* bout = (const float*)d_in[29];
    float* out = (float*)d_out;

    int smem = (int)sizeof(EdgeSmem);
    cudaFuncSetAttribute(edge_layer_kernel, cudaFuncAttributeMaxDynamicSharedMemorySize, smem);
    cudaFuncSetAttribute(head_kernel, cudaFuncAttributeMaxDynamicSharedMemorySize, smem);

    wprep_kernel<<<(5 * H_ * H_ + 255) / 256, 256>>>(Wu, Wm);
    gat_prep_kernel<<<BV_, 256>>>(coord, W_gat, att_src, att_dst);
    gat_softmax_kernel<<<BV_, 256>>>(x_edges);
    xinit_kernel<<<512, 256>>>(b_gat);
    gat_agg_kernel<<<dim3(4, 8, 16), 256>>>();
    edge_embed_kernel<<<EROWS_, 256>>>(x_ev, x_edges, W_ev, emb_e);

    for (int l = 0; l < L_; ++l) {
        zero_sums_kernel<<<1, 256>>>();
        node_lin4_kernel<<<dim3(16, 8, 4), 256>>>(
            Wv + l * H_ * H_, Wq + l * H_ * H_, Wk + l * H_ * H_, Wval + l * H_ * H_,
            bv + l * H_, bq + l * H_, bk + l * H_, bval + l * H_);
        edge_layer_kernel<<<512, 256, smem>>>(l, l > 0 ? 1 : 0, bu + l * H_);
        edge_bn_finalize_kernel<<<1, 256>>>(g_edge + l * H_, be_edge + l * H_);
        attn_kernel<<<dim3(128, 8, 4), 128>>>();
        node_lin1_kernel<<<dim3(16, 8), 256>>>(Wo + l * H_ * H_, bo + l * H_);
        node_bn_stats_kernel<<<16, 256>>>();
        node_update_kernel<<<BV_, 256>>>(g_node + l * H_, be_node + l * H_);
    }

    out_init_kernel<<<512, 256>>>(bout, out);
    head_kernel<<<512, 256, smem>>>(bm, Wout, out);
}